// round 10
// baseline (speedup 1.0000x reference)
#include <cuda_runtime.h>
#include <math.h>

// Self-convolution via real-packed shared-memory FFT: radix-8 fused passes,
// NT=512, packed f32x2 butterflies, scoped sync, table-free twiddles
// (w1 computed once per fwd/inv pass pair), zero-pad-aware pass1,
// register-fused center, and conflict-free smem padding (8 slots per 64).

#define SEQ_L   4096
#define OUT_L   (2 * SEQ_L - 1)     // 8191
#define FFT_M   4096
#define NT      512

#define IDX(a)  ((a) + (((a) >> 6) << 3))       // pad 8 slots per 64
#define RE_SZ   (FFT_M + ((FFT_M >> 6) << 3))   // 4608 complex slots (36 KB)
#define S8      0.70710678118654752440f
#define W_ANG   (-6.28318530717958647692f / (float)FFT_M)
#define N_ANG   (-6.28318530717958647692f / (float)(2 * FFT_M))

#define BAR_PAIR(tid) asm volatile("bar.sync %0, 64;" :: "r"(1 + ((tid) >> 6)) : "memory")

typedef unsigned long long q64;   // packed (float lo, float hi) complex

// ---------- packed f32x2 primitives ----------
__device__ __forceinline__ q64 qpk(float x, float y) {
    q64 r; asm("mov.b64 %0,{%1,%2};" : "=l"(r) : "f"(x), "f"(y)); return r;
}
__device__ __forceinline__ float2 qun(q64 a) {
    float2 f; asm("mov.b64 {%0,%1},%2;" : "=f"(f.x), "=f"(f.y) : "l"(a)); return f;
}
__device__ __forceinline__ q64 qswp(q64 a) {
    q64 r;
    asm("{\n\t.reg .b32 lo,hi;\n\tmov.b64 {lo,hi},%1;\n\tmov.b64 %0,{hi,lo};\n\t}"
        : "=l"(r) : "l"(a));
    return r;
}
__device__ __forceinline__ q64 qadd(q64 a, q64 b) {
    q64 r; asm("add.rn.f32x2 %0,%1,%2;" : "=l"(r) : "l"(a), "l"(b)); return r;
}
__device__ __forceinline__ q64 qmul(q64 a, q64 b) {
    q64 r; asm("mul.rn.f32x2 %0,%1,%2;" : "=l"(r) : "l"(a), "l"(b)); return r;
}
__device__ __forceinline__ q64 qfma(q64 a, q64 b, q64 c) {
    q64 r; asm("fma.rn.f32x2 %0,%1,%2,%3;" : "=l"(r) : "l"(a), "l"(b), "l"(c)); return r;
}
__device__ __forceinline__ q64 qsub(q64 a, q64 b, q64 n1) { return qfma(b, n1, a); }

struct qtw { q64 xx, sy; };
__device__ __forceinline__ qtw mk(float p, float q) {
    qtw t; t.xx = qpk(p, p); t.sy = qpk(-q, q); return t;
}
__device__ __forceinline__ q64 qcmul(q64 a, qtw t) {
    return qfma(qswp(a), t.sy, qmul(a, t.xx));
}

// ---------- scalar complex (center path; constants fold) ----------
__device__ __forceinline__ float2 cmul(float2 a, float2 w) {
    return make_float2(a.x * w.x - a.y * w.y, a.x * w.y + a.y * w.x);
}
__device__ __forceinline__ float2 cmulj(float2 a, float2 w) {
    return make_float2(a.x * w.x + a.y * w.y, a.y * w.x - a.x * w.y);
}
__device__ __forceinline__ float2 cadd(float2 a, float2 b) {
    return make_float2(a.x + b.x, a.y + b.y);
}
__device__ __forceinline__ float2 csub(float2 a, float2 b) {
    return make_float2(a.x - b.x, a.y - b.y);
}
__device__ __forceinline__ float2 twof(int t) {
    float2 w;
    __sincosf(W_ANG * (float)t, &w.y, &w.x);
    return w;
}

extern __shared__ q64 s_z[];

// ---------- packed radix-8 ----------
__device__ __forceinline__ void qfwd8_s23(q64 v[8], float2 w2, float2 w4, q64 n1) {
    const qtw T2  = mk(w2.x, w2.y);
    const qtw T2N = mk(w2.y, -w2.x);
    #pragma unroll
    for (int h = 0; h < 8; h += 4) {
        q64 u = qsub(v[h + 0], v[h + 2], n1);
        v[h + 0] = qadd(v[h + 0], v[h + 2]);
        v[h + 2] = qcmul(u, T2);
        u = qsub(v[h + 1], v[h + 3], n1);
        v[h + 1] = qadd(v[h + 1], v[h + 3]);
        v[h + 3] = qcmul(u, T2N);
    }
    const qtw T4 = mk(w4.x, w4.y);
    #pragma unroll
    for (int h = 0; h < 8; h += 2) {
        const q64 u = qsub(v[h], v[h + 1], n1);
        v[h] = qadd(v[h], v[h + 1]);
        v[h + 1] = qcmul(u, T4);
    }
}

__device__ __forceinline__ void qfwd8(q64 v[8], float2 w1, float2 w2, float2 w4, q64 n1) {
    const qtw T1 = mk(w1.x, w1.y);
    const qtw TB = mk(S8 * (w1.x + w1.y), S8 * (w1.y - w1.x));
    const qtw TC = mk(w1.y, -w1.x);
    const qtw TD = mk(-S8 * (w1.x - w1.y), -S8 * (w1.y + w1.x));

    q64 d0 = qsub(v[0], v[4], n1), d1 = qsub(v[1], v[5], n1);
    q64 d2 = qsub(v[2], v[6], n1), d3 = qsub(v[3], v[7], n1);
    v[0] = qadd(v[0], v[4]);
    v[1] = qadd(v[1], v[5]);
    v[2] = qadd(v[2], v[6]);
    v[3] = qadd(v[3], v[7]);
    v[4] = qcmul(d0, T1);
    v[5] = qcmul(d1, TB);
    v[6] = qcmul(d2, TC);
    v[7] = qcmul(d3, TD);

    qfwd8_s23(v, w2, w4, n1);
}

__device__ __forceinline__ void qinv8(q64 v[8], float2 w1, float2 w2, float2 w4, q64 n1) {
    const qtw T4C = mk(w4.x, -w4.y);
    #pragma unroll
    for (int h = 0; h < 8; h += 2) {
        const q64 t = qcmul(v[h + 1], T4C);
        v[h + 1] = qsub(v[h], t, n1);
        v[h]     = qadd(v[h], t);
    }
    const qtw T2C = mk(w2.x, -w2.y);
    const qtw T2I = mk(w2.y, w2.x);
    #pragma unroll
    for (int h = 0; h < 8; h += 4) {
        q64 t = qcmul(v[h + 2], T2C);
        v[h + 2] = qsub(v[h], t, n1);
        v[h]     = qadd(v[h], t);
        t = qcmul(v[h + 3], T2I);
        v[h + 3] = qsub(v[h + 1], t, n1);
        v[h + 1] = qadd(v[h + 1], t);
    }
    {
        const qtw T1C = mk(w1.x, -w1.y);
        const qtw TC1 = mk(S8 * (w1.x + w1.y), S8 * (w1.x - w1.y));
        const qtw TC2 = mk(w1.y, w1.x);
        const qtw TC3 = mk(-S8 * (w1.x - w1.y), S8 * (w1.y + w1.x));

        q64 t = qcmul(v[4], T1C);
        v[4] = qsub(v[0], t, n1);
        v[0] = qadd(v[0], t);
        t = qcmul(v[5], TC1);
        v[5] = qsub(v[1], t, n1);
        v[1] = qadd(v[1], t);
        t = qcmul(v[6], TC2);
        v[6] = qsub(v[2], t, n1);
        v[2] = qadd(v[2], t);
        t = qcmul(v[7], TC3);
        v[7] = qsub(v[3], t, n1);
        v[3] = qadd(v[3], t);
    }
}

// ---------- scalar radix-8 (center only; unit twiddles fold) ----------
__device__ __forceinline__ void fwd8_s23(float2* v, float2 w2, float2 w4) {
    #pragma unroll
    for (int h = 0; h < 8; h += 4) {
        float2 u = csub(v[h + 0], v[h + 2]);
        v[h + 0] = cadd(v[h + 0], v[h + 2]);
        v[h + 2] = cmul(u, w2);
        u = csub(v[h + 1], v[h + 3]);
        v[h + 1] = cadd(v[h + 1], v[h + 3]);
        v[h + 3] = make_float2(u.x * w2.y + u.y * w2.x,
                               u.y * w2.y - u.x * w2.x);
    }
    #pragma unroll
    for (int h = 0; h < 8; h += 2) {
        const float2 u = csub(v[h], v[h + 1]);
        v[h] = cadd(v[h], v[h + 1]);
        v[h + 1] = cmul(u, w4);
    }
}
__device__ __forceinline__ void fwd8(float2* v, float2 w1, float2 w2, float2 w4) {
    const float2 wb = make_float2(S8 * (w1.x + w1.y), S8 * (w1.y - w1.x));
    const float2 wc = make_float2(w1.y, -w1.x);
    const float2 wd = make_float2(-S8 * (w1.x - w1.y), -S8 * (w1.y + w1.x));
    float2 s0 = cadd(v[0], v[4]), d0 = csub(v[0], v[4]);
    float2 s1 = cadd(v[1], v[5]), d1 = csub(v[1], v[5]);
    float2 s2 = cadd(v[2], v[6]), d2 = csub(v[2], v[6]);
    float2 s3 = cadd(v[3], v[7]), d3 = csub(v[3], v[7]);
    v[0] = s0; v[1] = s1; v[2] = s2; v[3] = s3;
    v[4] = cmul(d0, w1);
    v[5] = cmul(d1, wb);
    v[6] = cmul(d2, wc);
    v[7] = cmul(d3, wd);
    fwd8_s23(v, w2, w4);
}
__device__ __forceinline__ void inv8(float2* v, float2 w1, float2 w2, float2 w4) {
    #pragma unroll
    for (int h = 0; h < 8; h += 2) {
        const float2 t = cmulj(v[h + 1], w4);
        v[h + 1] = csub(v[h], t);
        v[h]     = cadd(v[h], t);
    }
    #pragma unroll
    for (int h = 0; h < 8; h += 4) {
        float2 t = cmulj(v[h + 2], w2);
        v[h + 2] = csub(v[h], t);
        v[h]     = cadd(v[h], t);
        t = make_float2(v[h + 3].x * w2.y - v[h + 3].y * w2.x,
                        v[h + 3].x * w2.x + v[h + 3].y * w2.y);
        v[h + 3] = csub(v[h + 1], t);
        v[h + 1] = cadd(v[h + 1], t);
    }
    {
        float2 t = cmulj(v[4], w1);
        v[4] = csub(v[0], t);
        v[0] = cadd(v[0], t);
        const float2 c1 = make_float2(S8 * (w1.x + w1.y), S8 * (w1.x - w1.y));
        t = cmul(v[5], c1);
        v[5] = csub(v[1], t);
        v[1] = cadd(v[1], t);
        t = make_float2(v[6].x * w1.y - v[6].y * w1.x,
                        v[6].x * w1.x + v[6].y * w1.y);
        v[6] = csub(v[2], t);
        v[2] = cadd(v[2], t);
        const float2 c3 = make_float2(-S8 * (w1.x - w1.y), S8 * (w1.y + w1.x));
        t = cmul(v[7], c3);
        v[7] = csub(v[3], t);
        v[3] = cadd(v[3], t);
    }
}

// Untangle + square + repack one (kb, pb) mirror pair (scalar; center only).
__device__ __forceinline__ void midpair(float2& zk, float2& zm, int kb, float hm) {
    const int k = __brev((unsigned)kb) >> 20;
    float wi, wr;
    __sincosf(N_ANG * (float)k, &wi, &wr);

    const float Er = 0.5f * (zk.x + zm.x);
    const float Ei = 0.5f * (zk.y - zm.y);
    const float Or = 0.5f * (zk.y + zm.y);
    const float Oi = 0.5f * (zm.x - zk.x);

    const float WOr = Or * wr - Oi * wi;
    const float WOi = Or * wi + Oi * wr;

    const float Pr = Er + WOr, Pi = Ei + WOi;
    const float Qr = Er - WOr, Qi = Ei - WOi;

    const float P2r = Pr * Pr - Pi * Pi, P2i = 2.0f * Pr * Pi;
    const float Q2r = Qr * Qr - Qi * Qi, Q2i = 2.0f * Qr * Qi;

    const float Epr = hm * (P2r + Q2r);
    const float Epi = hm * (P2i + Q2i);
    const float Sr  = hm * (P2r - Q2r);
    const float Si  = hm * (P2i - Q2i);
    const float Opr = Sr * wr + Si * wi;
    const float Opi = Si * wr - Sr * wi;

    zk = make_float2(Epr - Opi, Epi + Opr);
    zm = make_float2(Epr + Opi, Opr - Epi);
}

__global__ void __launch_bounds__(NT, 1)
conv_self_rfft8p_kernel(const float* __restrict__ x, float* __restrict__ out) {
    q64* z = s_z;

    const int tid = threadIdx.x;
    const int b   = blockIdx.x;
    const q64 n1  = qpk(-1.0f, -1.0f);

    // twiddle bases, computed once, reused by mirror passes (1/D, 2/C, 3/B)
    const float2 w1a = twof(tid);               // pass1, passD
    const float2 w1b = twof((tid & 63) * 8);    // pass2, passC
    const float2 w1c = twof((tid & 7) * 64);    // pass3, passB

    // ---- Load lower half only (upper half structural zero) ----
    const q64* xb2 = (const q64*)(x + (size_t)b * SEQ_L);
    #pragma unroll
    for (int k = 0; k < 4; k++) {
        const int m = tid + k * NT;          // < 2048
        z[IDX(m)] = xb2[m];
    }
    // no barrier: pass1 reads exactly these thread-local slots

    // ---- fwd pass1: len=4096; upper inputs zero => stage1 degenerates
    {
        q64 v[8];
        #pragma unroll
        for (int k = 0; k < 4; k++) v[k] = z[IDX(tid + k * 512)];

        const float2 w2 = cmul(w1a, w1a);
        const float2 w4 = cmul(w2, w2);
        const qtw T1 = mk(w1a.x, w1a.y);
        const qtw TB = mk(S8 * (w1a.x + w1a.y), S8 * (w1a.y - w1a.x));
        const qtw TC = mk(w1a.y, -w1a.x);
        const qtw TD = mk(-S8 * (w1a.x - w1a.y), -S8 * (w1a.y + w1a.x));

        v[4] = qcmul(v[0], T1);
        v[5] = qcmul(v[1], TB);
        v[6] = qcmul(v[2], TC);
        v[7] = qcmul(v[3], TD);
        qfwd8_s23(v, w2, w4, n1);

        #pragma unroll
        for (int k = 0; k < 8; k++) z[IDX(tid + k * 512)] = v[k];
    }
    __syncthreads();

    // ---- fwd pass2: len=512 (64-thread groups), st=8
    {
        const int p = tid & 63;
        const int base = ((tid - p) << 3) + p;
        int ix[8];
        #pragma unroll
        for (int k = 0; k < 8; k++) ix[k] = IDX(base + k * 64);
        q64 v[8];
        #pragma unroll
        for (int k = 0; k < 8; k++) v[k] = z[ix[k]];
        const float2 w2 = cmul(w1b, w1b);
        const float2 w4 = cmul(w2, w2);
        qfwd8(v, w1b, w2, w4, n1);
        #pragma unroll
        for (int k = 0; k < 8; k++) z[ix[k]] = v[k];
    }
    BAR_PAIR(tid);

    // ---- fwd pass3: len=64 (warp-contained), st=64
    {
        const int p = tid & 7;
        const int base = ((tid - p) << 3) + p;
        int ix[8];
        #pragma unroll
        for (int k = 0; k < 8; k++) ix[k] = IDX(base + k * 8);
        q64 v[8];
        #pragma unroll
        for (int k = 0; k < 8; k++) v[k] = z[ix[k]];
        const float2 w2 = cmul(w1c, w1c);
        const float2 w4 = cmul(w2, w2);
        qfwd8(v, w1c, w2, w4, n1);
        #pragma unroll
        for (int k = 0; k < 8; k++) z[ix[k]] = v[k];
    }
    __syncthreads();   // center reads octets across warps

    // ---- Register-fused center: fwd pass4 + middle + inv passA on mirrored
    //      octet pairs (scalar math; unit twiddles fold).
    if (tid < 256) {
        int oa, oc;
        if (tid == 0) { oa = 0; oc = 1; }
        else {
            const int msbu = 1 << (31 - __clz(tid));
            const int O = msbu << 1;
            oa = O + (tid - msbu);
            oc = 3 * O - 1 - oa;
        }

        float2 a[8], c[8];
        {
            const float4* pa = (const float4*)&z[IDX(8 * oa)];
            const float4* pc = (const float4*)&z[IDX(8 * oc)];
            #pragma unroll
            for (int i = 0; i < 4; i++) {
                float4 va = pa[i], vc = pc[i];
                a[2 * i]     = make_float2(va.x, va.y);
                a[2 * i + 1] = make_float2(va.z, va.w);
                c[2 * i]     = make_float2(vc.x, vc.y);
                c[2 * i + 1] = make_float2(vc.z, vc.w);
            }
        }

        const float2 one = make_float2(1.f, 0.f);
        fwd8(a, one, one, one);
        fwd8(c, one, one, one);

        const float hm = 0.5f / (float)FFT_M;
        if (tid == 0) {
            {
                const float P = a[0].x + a[0].y, Q = a[0].x - a[0].y;
                const float P2 = P * P, Q2 = Q * Q;
                a[0] = make_float2(hm * (P2 + Q2), hm * (P2 - Q2));
                a[1] = make_float2(2.0f * hm * (a[1].x * a[1].x - a[1].y * a[1].y),
                                   2.0f * hm * (2.0f * a[1].x * a[1].y));
            }
            midpair(a[2], a[3], 2, hm);
            midpair(a[4], a[7], 4, hm);
            midpair(a[5], a[6], 5, hm);
            midpair(c[0], c[7], 8, hm);
            midpair(c[1], c[6], 9, hm);
            midpair(c[2], c[5], 10, hm);
            midpair(c[3], c[4], 11, hm);
        } else {
            const int kb0 = 8 * oa;
            #pragma unroll
            for (int r = 0; r < 8; r++)
                midpair(a[r], c[7 - r], kb0 + r, hm);
        }

        inv8(a, one, one, one);
        inv8(c, one, one, one);

        {
            float4* pa = (float4*)&z[IDX(8 * oa)];
            float4* pc = (float4*)&z[IDX(8 * oc)];
            #pragma unroll
            for (int i = 0; i < 4; i++) {
                pa[i] = make_float4(a[2 * i].x, a[2 * i].y,
                                    a[2 * i + 1].x, a[2 * i + 1].y);
                pc[i] = make_float4(c[2 * i].x, c[2 * i].y,
                                    c[2 * i + 1].x, c[2 * i + 1].y);
            }
        }
    }
    __syncthreads();

    // ---- inv passB: lenBig=64 (warp-contained), st=64
    {
        const int p = tid & 7;
        const int base = ((tid - p) << 3) + p;
        int ix[8];
        #pragma unroll
        for (int k = 0; k < 8; k++) ix[k] = IDX(base + k * 8);
        q64 v[8];
        #pragma unroll
        for (int k = 0; k < 8; k++) v[k] = z[ix[k]];
        const float2 w2 = cmul(w1c, w1c);
        const float2 w4 = cmul(w2, w2);
        qinv8(v, w1c, w2, w4, n1);
        #pragma unroll
        for (int k = 0; k < 8; k++) z[ix[k]] = v[k];
    }
    BAR_PAIR(tid);

    // ---- inv passC: lenBig=512 (64-thread groups), st=8
    {
        const int p = tid & 63;
        const int base = ((tid - p) << 3) + p;
        int ix[8];
        #pragma unroll
        for (int k = 0; k < 8; k++) ix[k] = IDX(base + k * 64);
        q64 v[8];
        #pragma unroll
        for (int k = 0; k < 8; k++) v[k] = z[ix[k]];
        const float2 w2 = cmul(w1b, w1b);
        const float2 w4 = cmul(w2, w2);
        qinv8(v, w1b, w2, w4, n1);
        #pragma unroll
        for (int k = 0; k < 8; k++) z[ix[k]] = v[k];
    }
    __syncthreads();

    // ---- inv passD: lenBig=4096, thread-local slots (tid + 512k)
    q64 v[8];
    {
        #pragma unroll
        for (int k = 0; k < 8; k++) v[k] = z[IDX(tid + k * 512)];
        const float2 w2 = cmul(w1a, w1a);
        const float2 w4 = cmul(w2, w2);
        qinv8(v, w1a, w2, w4, n1);
    }
    // no barrier: store reads this thread's registers

    // ---- Store (already scaled). Only tid=511,k=7 hits the 8191 edge.
    float* ob = out + (size_t)b * OUT_L;
    #pragma unroll
    for (int k = 0; k < 7; k++) {
        const int m = tid + k * 512;
        const float2 f = qun(v[k]);
        ob[2 * m]     = f.x;
        ob[2 * m + 1] = f.y;
    }
    {
        const int m = tid + 7 * 512;
        const float2 f = qun(v[7]);
        ob[2 * m] = f.x;
        if (tid != 511) ob[2 * m + 1] = f.y;
    }
}

extern "C" void kernel_launch(void* const* d_in, const int* in_sizes, int n_in,
                              void* d_out, int out_size) {
    (void)in_sizes; (void)n_in; (void)out_size;
    const float* x = (const float*)d_in[0];
    float* out = (float*)d_out;

    const int smem_bytes = RE_SZ * (int)sizeof(q64);  // 36 KB
    cudaFuncSetAttribute(conv_self_rfft8p_kernel,
                         cudaFuncAttributeMaxDynamicSharedMemorySize, smem_bytes);

    conv_self_rfft8p_kernel<<<128, NT, smem_bytes>>>(x, out);
}

// round 11
// speedup vs baseline: 1.2362x; 1.2362x over previous
#include <cuda_runtime.h>
#include <math.h>

// Self-convolution via real-packed shared-memory FFT: radix-8 fused passes,
// NT=512, packed f32x2 butterflies, scoped sync, table-free twiddles
// (w1 computed once per fwd/inv pass pair), zero-pad-aware pass1 with inputs
// loaded DIRECTLY from gmem into registers (no smem round-trip), register-
// fused center, R9 padding (2 slots per 16).

#define SEQ_L   4096
#define OUT_L   (2 * SEQ_L - 1)     // 8191
#define FFT_M   4096
#define NT      512

#define IDX(a)  ((a) + (((a) >> 4) << 1))       // pad 2 slots per 16 (R9 best)
#define RE_SZ   (FFT_M + ((FFT_M >> 4) << 1))   // 4608 complex slots (36 KB)
#define S8      0.70710678118654752440f
#define W_ANG   (-6.28318530717958647692f / (float)FFT_M)
#define N_ANG   (-6.28318530717958647692f / (float)(2 * FFT_M))

#define BAR_PAIR(tid) asm volatile("bar.sync %0, 64;" :: "r"(1 + ((tid) >> 6)) : "memory")

typedef unsigned long long q64;   // packed (float lo, float hi) complex

// ---------- packed f32x2 primitives ----------
__device__ __forceinline__ q64 qpk(float x, float y) {
    q64 r; asm("mov.b64 %0,{%1,%2};" : "=l"(r) : "f"(x), "f"(y)); return r;
}
__device__ __forceinline__ float2 qun(q64 a) {
    float2 f; asm("mov.b64 {%0,%1},%2;" : "=f"(f.x), "=f"(f.y) : "l"(a)); return f;
}
__device__ __forceinline__ q64 qswp(q64 a) {
    q64 r;
    asm("{\n\t.reg .b32 lo,hi;\n\tmov.b64 {lo,hi},%1;\n\tmov.b64 %0,{hi,lo};\n\t}"
        : "=l"(r) : "l"(a));
    return r;
}
__device__ __forceinline__ q64 qadd(q64 a, q64 b) {
    q64 r; asm("add.rn.f32x2 %0,%1,%2;" : "=l"(r) : "l"(a), "l"(b)); return r;
}
__device__ __forceinline__ q64 qmul(q64 a, q64 b) {
    q64 r; asm("mul.rn.f32x2 %0,%1,%2;" : "=l"(r) : "l"(a), "l"(b)); return r;
}
__device__ __forceinline__ q64 qfma(q64 a, q64 b, q64 c) {
    q64 r; asm("fma.rn.f32x2 %0,%1,%2,%3;" : "=l"(r) : "l"(a), "l"(b), "l"(c)); return r;
}
__device__ __forceinline__ q64 qsub(q64 a, q64 b, q64 n1) { return qfma(b, n1, a); }

struct qtw { q64 xx, sy; };
__device__ __forceinline__ qtw mk(float p, float q) {
    qtw t; t.xx = qpk(p, p); t.sy = qpk(-q, q); return t;
}
__device__ __forceinline__ q64 qcmul(q64 a, qtw t) {
    return qfma(qswp(a), t.sy, qmul(a, t.xx));
}

// ---------- scalar complex (center path; constants fold) ----------
__device__ __forceinline__ float2 cmul(float2 a, float2 w) {
    return make_float2(a.x * w.x - a.y * w.y, a.x * w.y + a.y * w.x);
}
__device__ __forceinline__ float2 cmulj(float2 a, float2 w) {
    return make_float2(a.x * w.x + a.y * w.y, a.y * w.x - a.x * w.y);
}
__device__ __forceinline__ float2 cadd(float2 a, float2 b) {
    return make_float2(a.x + b.x, a.y + b.y);
}
__device__ __forceinline__ float2 csub(float2 a, float2 b) {
    return make_float2(a.x - b.x, a.y - b.y);
}
__device__ __forceinline__ float2 twof(int t) {
    float2 w;
    __sincosf(W_ANG * (float)t, &w.y, &w.x);
    return w;
}

extern __shared__ q64 s_z[];

// ---------- packed radix-8 ----------
__device__ __forceinline__ void qfwd8_s23(q64 v[8], float2 w2, float2 w4, q64 n1) {
    const qtw T2  = mk(w2.x, w2.y);
    const qtw T2N = mk(w2.y, -w2.x);
    #pragma unroll
    for (int h = 0; h < 8; h += 4) {
        q64 u = qsub(v[h + 0], v[h + 2], n1);
        v[h + 0] = qadd(v[h + 0], v[h + 2]);
        v[h + 2] = qcmul(u, T2);
        u = qsub(v[h + 1], v[h + 3], n1);
        v[h + 1] = qadd(v[h + 1], v[h + 3]);
        v[h + 3] = qcmul(u, T2N);
    }
    const qtw T4 = mk(w4.x, w4.y);
    #pragma unroll
    for (int h = 0; h < 8; h += 2) {
        const q64 u = qsub(v[h], v[h + 1], n1);
        v[h] = qadd(v[h], v[h + 1]);
        v[h + 1] = qcmul(u, T4);
    }
}

__device__ __forceinline__ void qfwd8(q64 v[8], float2 w1, float2 w2, float2 w4, q64 n1) {
    const qtw T1 = mk(w1.x, w1.y);
    const qtw TB = mk(S8 * (w1.x + w1.y), S8 * (w1.y - w1.x));
    const qtw TC = mk(w1.y, -w1.x);
    const qtw TD = mk(-S8 * (w1.x - w1.y), -S8 * (w1.y + w1.x));

    q64 d0 = qsub(v[0], v[4], n1), d1 = qsub(v[1], v[5], n1);
    q64 d2 = qsub(v[2], v[6], n1), d3 = qsub(v[3], v[7], n1);
    v[0] = qadd(v[0], v[4]);
    v[1] = qadd(v[1], v[5]);
    v[2] = qadd(v[2], v[6]);
    v[3] = qadd(v[3], v[7]);
    v[4] = qcmul(d0, T1);
    v[5] = qcmul(d1, TB);
    v[6] = qcmul(d2, TC);
    v[7] = qcmul(d3, TD);

    qfwd8_s23(v, w2, w4, n1);
}

__device__ __forceinline__ void qinv8(q64 v[8], float2 w1, float2 w2, float2 w4, q64 n1) {
    const qtw T4C = mk(w4.x, -w4.y);
    #pragma unroll
    for (int h = 0; h < 8; h += 2) {
        const q64 t = qcmul(v[h + 1], T4C);
        v[h + 1] = qsub(v[h], t, n1);
        v[h]     = qadd(v[h], t);
    }
    const qtw T2C = mk(w2.x, -w2.y);
    const qtw T2I = mk(w2.y, w2.x);
    #pragma unroll
    for (int h = 0; h < 8; h += 4) {
        q64 t = qcmul(v[h + 2], T2C);
        v[h + 2] = qsub(v[h], t, n1);
        v[h]     = qadd(v[h], t);
        t = qcmul(v[h + 3], T2I);
        v[h + 3] = qsub(v[h + 1], t, n1);
        v[h + 1] = qadd(v[h + 1], t);
    }
    {
        const qtw T1C = mk(w1.x, -w1.y);
        const qtw TC1 = mk(S8 * (w1.x + w1.y), S8 * (w1.x - w1.y));
        const qtw TC2 = mk(w1.y, w1.x);
        const qtw TC3 = mk(-S8 * (w1.x - w1.y), S8 * (w1.y + w1.x));

        q64 t = qcmul(v[4], T1C);
        v[4] = qsub(v[0], t, n1);
        v[0] = qadd(v[0], t);
        t = qcmul(v[5], TC1);
        v[5] = qsub(v[1], t, n1);
        v[1] = qadd(v[1], t);
        t = qcmul(v[6], TC2);
        v[6] = qsub(v[2], t, n1);
        v[2] = qadd(v[2], t);
        t = qcmul(v[7], TC3);
        v[7] = qsub(v[3], t, n1);
        v[3] = qadd(v[3], t);
    }
}

// ---------- scalar radix-8 (center only; unit twiddles fold) ----------
__device__ __forceinline__ void fwd8_s23(float2* v, float2 w2, float2 w4) {
    #pragma unroll
    for (int h = 0; h < 8; h += 4) {
        float2 u = csub(v[h + 0], v[h + 2]);
        v[h + 0] = cadd(v[h + 0], v[h + 2]);
        v[h + 2] = cmul(u, w2);
        u = csub(v[h + 1], v[h + 3]);
        v[h + 1] = cadd(v[h + 1], v[h + 3]);
        v[h + 3] = make_float2(u.x * w2.y + u.y * w2.x,
                               u.y * w2.y - u.x * w2.x);
    }
    #pragma unroll
    for (int h = 0; h < 8; h += 2) {
        const float2 u = csub(v[h], v[h + 1]);
        v[h] = cadd(v[h], v[h + 1]);
        v[h + 1] = cmul(u, w4);
    }
}
__device__ __forceinline__ void fwd8(float2* v, float2 w1, float2 w2, float2 w4) {
    const float2 wb = make_float2(S8 * (w1.x + w1.y), S8 * (w1.y - w1.x));
    const float2 wc = make_float2(w1.y, -w1.x);
    const float2 wd = make_float2(-S8 * (w1.x - w1.y), -S8 * (w1.y + w1.x));
    float2 s0 = cadd(v[0], v[4]), d0 = csub(v[0], v[4]);
    float2 s1 = cadd(v[1], v[5]), d1 = csub(v[1], v[5]);
    float2 s2 = cadd(v[2], v[6]), d2 = csub(v[2], v[6]);
    float2 s3 = cadd(v[3], v[7]), d3 = csub(v[3], v[7]);
    v[0] = s0; v[1] = s1; v[2] = s2; v[3] = s3;
    v[4] = cmul(d0, w1);
    v[5] = cmul(d1, wb);
    v[6] = cmul(d2, wc);
    v[7] = cmul(d3, wd);
    fwd8_s23(v, w2, w4);
}
__device__ __forceinline__ void inv8(float2* v, float2 w1, float2 w2, float2 w4) {
    #pragma unroll
    for (int h = 0; h < 8; h += 2) {
        const float2 t = cmulj(v[h + 1], w4);
        v[h + 1] = csub(v[h], t);
        v[h]     = cadd(v[h], t);
    }
    #pragma unroll
    for (int h = 0; h < 8; h += 4) {
        float2 t = cmulj(v[h + 2], w2);
        v[h + 2] = csub(v[h], t);
        v[h]     = cadd(v[h], t);
        t = make_float2(v[h + 3].x * w2.y - v[h + 3].y * w2.x,
                        v[h + 3].x * w2.x + v[h + 3].y * w2.y);
        v[h + 3] = csub(v[h + 1], t);
        v[h + 1] = cadd(v[h + 1], t);
    }
    {
        float2 t = cmulj(v[4], w1);
        v[4] = csub(v[0], t);
        v[0] = cadd(v[0], t);
        const float2 c1 = make_float2(S8 * (w1.x + w1.y), S8 * (w1.x - w1.y));
        t = cmul(v[5], c1);
        v[5] = csub(v[1], t);
        v[1] = cadd(v[1], t);
        t = make_float2(v[6].x * w1.y - v[6].y * w1.x,
                        v[6].x * w1.x + v[6].y * w1.y);
        v[6] = csub(v[2], t);
        v[2] = cadd(v[2], t);
        const float2 c3 = make_float2(-S8 * (w1.x - w1.y), S8 * (w1.y + w1.x));
        t = cmul(v[7], c3);
        v[7] = csub(v[3], t);
        v[3] = cadd(v[3], t);
    }
}

// Untangle + square + repack one (kb, pb) mirror pair (scalar; center only).
__device__ __forceinline__ void midpair(float2& zk, float2& zm, int kb, float hm) {
    const int k = __brev((unsigned)kb) >> 20;
    float wi, wr;
    __sincosf(N_ANG * (float)k, &wi, &wr);

    const float Er = 0.5f * (zk.x + zm.x);
    const float Ei = 0.5f * (zk.y - zm.y);
    const float Or = 0.5f * (zk.y + zm.y);
    const float Oi = 0.5f * (zm.x - zk.x);

    const float WOr = Or * wr - Oi * wi;
    const float WOi = Or * wi + Oi * wr;

    const float Pr = Er + WOr, Pi = Ei + WOi;
    const float Qr = Er - WOr, Qi = Ei - WOi;

    const float P2r = Pr * Pr - Pi * Pi, P2i = 2.0f * Pr * Pi;
    const float Q2r = Qr * Qr - Qi * Qi, Q2i = 2.0f * Qr * Qi;

    const float Epr = hm * (P2r + Q2r);
    const float Epi = hm * (P2i + Q2i);
    const float Sr  = hm * (P2r - Q2r);
    const float Si  = hm * (P2i - Q2i);
    const float Opr = Sr * wr + Si * wi;
    const float Opi = Si * wr - Sr * wi;

    zk = make_float2(Epr - Opi, Epi + Opr);
    zm = make_float2(Epr + Opi, Opr - Epi);
}

__global__ void __launch_bounds__(NT, 1)
conv_self_rfft8r_kernel(const float* __restrict__ x, float* __restrict__ out) {
    q64* z = s_z;

    const int tid = threadIdx.x;
    const int b   = blockIdx.x;
    const q64 n1  = qpk(-1.0f, -1.0f);

    // twiddle bases, computed once, reused by mirror passes (1/D, 2/C, 3/B)
    const float2 w1a = twof(tid);               // pass1, passD
    const float2 w1b = twof((tid & 63) * 8);    // pass2, passC
    const float2 w1c = twof((tid & 7) * 64);    // pass3, passB

    // ---- fwd pass1: len=4096. Inputs come STRAIGHT from gmem (slots
    //      tid+512k, k<4, are exactly gmem elements tid+512k; k>=4 are the
    //      structural zero pad => stage1 degenerates). No smem on input.
    const q64* xb2 = (const q64*)(x + (size_t)b * SEQ_L);
    {
        q64 v[8];
        #pragma unroll
        for (int k = 0; k < 4; k++) v[k] = xb2[tid + k * 512];

        const float2 w2 = cmul(w1a, w1a);
        const float2 w4 = cmul(w2, w2);
        const qtw T1 = mk(w1a.x, w1a.y);
        const qtw TB = mk(S8 * (w1a.x + w1a.y), S8 * (w1a.y - w1a.x));
        const qtw TC = mk(w1a.y, -w1a.x);
        const qtw TD = mk(-S8 * (w1a.x - w1a.y), -S8 * (w1a.y + w1a.x));

        v[4] = qcmul(v[0], T1);
        v[5] = qcmul(v[1], TB);
        v[6] = qcmul(v[2], TC);
        v[7] = qcmul(v[3], TD);
        qfwd8_s23(v, w2, w4, n1);

        #pragma unroll
        for (int k = 0; k < 8; k++) z[IDX(tid + k * 512)] = v[k];
    }
    __syncthreads();

    // ---- fwd pass2: len=512 (64-thread groups), st=8
    {
        const int p = tid & 63;
        const int base = ((tid - p) << 3) + p;
        int ix[8];
        #pragma unroll
        for (int k = 0; k < 8; k++) ix[k] = IDX(base + k * 64);
        q64 v[8];
        #pragma unroll
        for (int k = 0; k < 8; k++) v[k] = z[ix[k]];
        const float2 w2 = cmul(w1b, w1b);
        const float2 w4 = cmul(w2, w2);
        qfwd8(v, w1b, w2, w4, n1);
        #pragma unroll
        for (int k = 0; k < 8; k++) z[ix[k]] = v[k];
    }
    BAR_PAIR(tid);

    // ---- fwd pass3: len=64 (warp-contained), st=64
    {
        const int p = tid & 7;
        const int base = ((tid - p) << 3) + p;
        int ix[8];
        #pragma unroll
        for (int k = 0; k < 8; k++) ix[k] = IDX(base + k * 8);
        q64 v[8];
        #pragma unroll
        for (int k = 0; k < 8; k++) v[k] = z[ix[k]];
        const float2 w2 = cmul(w1c, w1c);
        const float2 w4 = cmul(w2, w2);
        qfwd8(v, w1c, w2, w4, n1);
        #pragma unroll
        for (int k = 0; k < 8; k++) z[ix[k]] = v[k];
    }
    __syncthreads();   // center reads octets across warps

    // ---- Register-fused center: fwd pass4 + middle + inv passA on mirrored
    //      octet pairs (scalar math; unit twiddles fold).
    if (tid < 256) {
        int oa, oc;
        if (tid == 0) { oa = 0; oc = 1; }
        else {
            const int msbu = 1 << (31 - __clz(tid));
            const int O = msbu << 1;
            oa = O + (tid - msbu);
            oc = 3 * O - 1 - oa;
        }

        float2 a[8], c[8];
        {
            const float4* pa = (const float4*)&z[IDX(8 * oa)];
            const float4* pc = (const float4*)&z[IDX(8 * oc)];
            #pragma unroll
            for (int i = 0; i < 4; i++) {
                float4 va = pa[i], vc = pc[i];
                a[2 * i]     = make_float2(va.x, va.y);
                a[2 * i + 1] = make_float2(va.z, va.w);
                c[2 * i]     = make_float2(vc.x, vc.y);
                c[2 * i + 1] = make_float2(vc.z, vc.w);
            }
        }

        const float2 one = make_float2(1.f, 0.f);
        fwd8(a, one, one, one);
        fwd8(c, one, one, one);

        const float hm = 0.5f / (float)FFT_M;
        if (tid == 0) {
            {
                const float P = a[0].x + a[0].y, Q = a[0].x - a[0].y;
                const float P2 = P * P, Q2 = Q * Q;
                a[0] = make_float2(hm * (P2 + Q2), hm * (P2 - Q2));
                a[1] = make_float2(2.0f * hm * (a[1].x * a[1].x - a[1].y * a[1].y),
                                   2.0f * hm * (2.0f * a[1].x * a[1].y));
            }
            midpair(a[2], a[3], 2, hm);
            midpair(a[4], a[7], 4, hm);
            midpair(a[5], a[6], 5, hm);
            midpair(c[0], c[7], 8, hm);
            midpair(c[1], c[6], 9, hm);
            midpair(c[2], c[5], 10, hm);
            midpair(c[3], c[4], 11, hm);
        } else {
            const int kb0 = 8 * oa;
            #pragma unroll
            for (int r = 0; r < 8; r++)
                midpair(a[r], c[7 - r], kb0 + r, hm);
        }

        inv8(a, one, one, one);
        inv8(c, one, one, one);

        {
            float4* pa = (float4*)&z[IDX(8 * oa)];
            float4* pc = (float4*)&z[IDX(8 * oc)];
            #pragma unroll
            for (int i = 0; i < 4; i++) {
                pa[i] = make_float4(a[2 * i].x, a[2 * i].y,
                                    a[2 * i + 1].x, a[2 * i + 1].y);
                pc[i] = make_float4(c[2 * i].x, c[2 * i].y,
                                    c[2 * i + 1].x, c[2 * i + 1].y);
            }
        }
    }
    __syncthreads();

    // ---- inv passB: lenBig=64 (warp-contained), st=64
    {
        const int p = tid & 7;
        const int base = ((tid - p) << 3) + p;
        int ix[8];
        #pragma unroll
        for (int k = 0; k < 8; k++) ix[k] = IDX(base + k * 8);
        q64 v[8];
        #pragma unroll
        for (int k = 0; k < 8; k++) v[k] = z[ix[k]];
        const float2 w2 = cmul(w1c, w1c);
        const float2 w4 = cmul(w2, w2);
        qinv8(v, w1c, w2, w4, n1);
        #pragma unroll
        for (int k = 0; k < 8; k++) z[ix[k]] = v[k];
    }
    BAR_PAIR(tid);

    // ---- inv passC: lenBig=512 (64-thread groups), st=8
    {
        const int p = tid & 63;
        const int base = ((tid - p) << 3) + p;
        int ix[8];
        #pragma unroll
        for (int k = 0; k < 8; k++) ix[k] = IDX(base + k * 64);
        q64 v[8];
        #pragma unroll
        for (int k = 0; k < 8; k++) v[k] = z[ix[k]];
        const float2 w2 = cmul(w1b, w1b);
        const float2 w4 = cmul(w2, w2);
        qinv8(v, w1b, w2, w4, n1);
        #pragma unroll
        for (int k = 0; k < 8; k++) z[ix[k]] = v[k];
    }
    __syncthreads();

    // ---- inv passD: lenBig=4096, thread-local slots (tid + 512k)
    q64 v[8];
    {
        #pragma unroll
        for (int k = 0; k < 8; k++) v[k] = z[IDX(tid + k * 512)];
        const float2 w2 = cmul(w1a, w1a);
        const float2 w4 = cmul(w2, w2);
        qinv8(v, w1a, w2, w4, n1);
    }
    // no barrier: store reads this thread's registers

    // ---- Store (already scaled). Only tid=511,k=7 hits the 8191 edge.
    float* ob = out + (size_t)b * OUT_L;
    #pragma unroll
    for (int k = 0; k < 7; k++) {
        const int m = tid + k * 512;
        const float2 f = qun(v[k]);
        ob[2 * m]     = f.x;
        ob[2 * m + 1] = f.y;
    }
    {
        const int m = tid + 7 * 512;
        const float2 f = qun(v[7]);
        ob[2 * m] = f.x;
        if (tid != 511) ob[2 * m + 1] = f.y;
    }
}

extern "C" void kernel_launch(void* const* d_in, const int* in_sizes, int n_in,
                              void* d_out, int out_size) {
    (void)in_sizes; (void)n_in; (void)out_size;
    const float* x = (const float*)d_in[0];
    float* out = (float*)d_out;

    const int smem_bytes = RE_SZ * (int)sizeof(q64);  // 36 KB
    cudaFuncSetAttribute(conv_self_rfft8r_kernel,
                         cudaFuncAttributeMaxDynamicSharedMemorySize, smem_bytes);

    conv_self_rfft8r_kernel<<<128, NT, smem_bytes>>>(x, out);
}